// round 16
// baseline (speedup 1.0000x reference)
#include <cuda_runtime.h>
#include <cuda_bf16.h>
#include <cuda_fp16.h>

#define BB 4
#define SS 1024
#define HH 16
#define HDIM 64
#define DD 1024

// ---------------------------------------------------------------------------
// scratch (device globals — no allocation allowed)
// ---------------------------------------------------------------------------
__device__ __half g_xh[BB * SS * DD];           // x fp16
__device__ __half g_wqT[3 * DD * DD];           // W_qkv^T fp16, permuted rows [Q|K|V]
__device__ float  g_bq[3 * DD];                 // permuted bias
__device__ __half g_woT[DD * DD];               // W_o^T fp16
__device__ __half g_vh[BB * SS * DD];           // values fp16 (attn epilogue)
__device__ __half g_qh[BB * SS * 3 * DD];       // qkv hi, permuted cols [Q|K|V]
__device__ __half g_ql[BB * SS * 3 * DD];       // qkv lo (only Q cols used)
__device__ __half g_vTh[BB * HH * HDIM * SS];   // V^T fp16 per (b,h): [64][S]

// ---------------------------------------------------------------------------
__device__ __forceinline__ unsigned smem_u32(const void* p) {
    unsigned a;
    asm("{ .reg .u64 t; cvta.to.shared.u64 t, %1; cvt.u32.u64 %0, t; }" : "=r"(a) : "l"(p));
    return a;
}
#define SWZ128(o) ((o) ^ (((o) >> 3) & 0x70))
#define SWZ64(o)  ((o) ^ (((o) >> 3) & 0x30))

#define CP_ASYNC16(saddr, gptr) \
    asm volatile("cp.async.cg.shared.global [%0], [%1], 16;" :: "r"(saddr), "l"(gptr) : "memory")
#define CP_COMMIT() asm volatile("cp.async.commit_group;" ::: "memory")
#define CP_WAIT1()  asm volatile("cp.async.wait_group 1;" ::: "memory")
#define CP_WAIT0()  asm volatile("cp.async.wait_group 0;" ::: "memory")

#define LDMX4(r0, r1, r2, r3, a) \
    asm volatile("ldmatrix.sync.aligned.m8n8.x4.shared.b16 {%0,%1,%2,%3}, [%4];" \
        : "=r"(r0), "=r"(r1), "=r"(r2), "=r"(r3) : "r"(a))

#define MMAF16(d, a, b0, b1) \
    asm volatile("mma.sync.aligned.m16n8k16.row.col.f32.f16.f16.f32 " \
        "{%0,%1,%2,%3}, {%4,%5,%6,%7}, {%8,%9}, {%0,%1,%2,%3};" \
        : "+f"((d)[0]), "+f"((d)[1]), "+f"((d)[2]), "+f"((d)[3]) \
        : "r"((a)[0]), "r"((a)[1]), "r"((a)[2]), "r"((a)[3]), "r"(b0), "r"(b1))

__device__ __forceinline__ unsigned packh2(float x, float y, unsigned& lo) {
    __half hx = __float2half(x);
    __half hy = __float2half(y);
    __half lx = __float2half(x - __half2float(hx));
    __half ly = __float2half(y - __half2float(hy));
    lo = ((unsigned)__half_as_ushort(ly) << 16) | __half_as_ushort(lx);
    return ((unsigned)__half_as_ushort(hy) << 16) | __half_as_ushort(hx);
}
__device__ __forceinline__ unsigned packs2(float x, float y) {
    return ((unsigned)__half_as_ushort(__float2half(y)) << 16) |
           __half_as_ushort(__float2half(x));
}
__device__ __forceinline__ int qkv_perm(int n) {
    int head = n / 192, wi = n % 192;
    return (wi / 64) * 1024 + head * 64 + (wi % 64);
}

// ---------------------------------------------------------------------------
__global__ __launch_bounds__(256) void cvt_kernel(
    const float* __restrict__ src, __half* __restrict__ dst, int n4)
{
    int i = blockIdx.x * 256 + threadIdx.x;
    if (i >= n4) return;
    float4 v = ((const float4*)src)[i];
    ((uint2*)dst)[i] = make_uint2(packs2(v.x, v.y), packs2(v.z, v.w));
}

__global__ __launch_bounds__(256) void tsingle_kernel(
    const float* __restrict__ W, __half* __restrict__ WT, int K, int N, int permute,
    const float* __restrict__ b, float* __restrict__ bp)
{
    __shared__ float t[32][33];
    int k0 = blockIdx.y * 32, n0 = blockIdx.x * 32;
    int tx = threadIdx.x, ty = threadIdx.y;
    #pragma unroll
    for (int i = 0; i < 32; i += 8)
        t[ty + i][tx] = W[(size_t)(k0 + ty + i) * N + n0 + tx];
    __syncthreads();
    #pragma unroll
    for (int i = 0; i < 32; i += 8) {
        int n = n0 + ty + i;
        int np = permute ? qkv_perm(n) : n;
        WT[(size_t)np * K + k0 + tx] = __float2half(t[tx][ty + i]);
    }
    if (b && blockIdx.y == 0) {
        int tid = ty * 32 + tx;
        if (tid < 32) {
            int n = n0 + tid;
            bp[permute ? qkv_perm(n) : n] = b[n];
        }
    }
}

__global__ __launch_bounds__(256) void vT_kernel(
    const __half* __restrict__ qh, __half* __restrict__ vTh)
{
    __shared__ __half t[32][33];
    int s0 = blockIdx.x * 32, d0 = blockIdx.y * 32, bh = blockIdx.z;
    int b = bh >> 4, h = bh & 15;
    int tx = threadIdx.x, ty = threadIdx.y;
    #pragma unroll
    for (int i = 0; i < 32; i += 8)
        t[ty + i][tx] = qh[(size_t)(b * SS + s0 + ty + i) * 3072 + 2048 + h * 64 + d0 + tx];
    __syncthreads();
    #pragma unroll
    for (int i = 0; i < 32; i += 8)
        vTh[(size_t)(bh * HDIM + d0 + ty + i) * SS + s0 + tx] = t[tx][ty + i];
}

// ---------------------------------------------------------------------------
__device__ __forceinline__ void gload64h(const __half* __restrict__ src,
                                         int rbase, int K, int kt, unsigned dst, int tid)
{
    #pragma unroll
    for (int i = 0; i < 4; i++) {
        int idx = tid + i * 128;
        int row = idx >> 2;
        int c16 = (idx & 3) * 16;
        CP_ASYNC16(dst + SWZ64((unsigned)(row * 64 + c16)),
                   (const char*)(src + (size_t)(rbase + row) * K + kt) + c16);
    }
}

// ---------------------------------------------------------------------------
// 1-pass fp16 GEMM: C fp32 | Q-cols hi/lo split | single fp16 (per bcol)
// ---------------------------------------------------------------------------
#define G1_STAGE 16384
#define G1_TOTAL 49152

__device__ __forceinline__ void prefetch_chunk1(
    const __half* __restrict__ A, const __half* __restrict__ BT,
    int brow, int bcol, int K, int kt, unsigned stage, int tid)
{
    gload64h(A, brow, K, kt, stage, tid);
    gload64h(BT, bcol, K, kt, stage + 8192, tid);
}

__global__ __launch_bounds__(128, 2) void gemm1x_mma(
    const __half* __restrict__ A, const __half* __restrict__ BT,
    const float* __restrict__ bias, float* __restrict__ C,
    __half* __restrict__ Chi, __half* __restrict__ Clo,
    int M, int Nstr, int K)
{
    extern __shared__ char smem[];
    unsigned sb = smem_u32(smem);
    const int tid = threadIdx.x, w = tid >> 5, lane = tid & 31;
    const int brow = blockIdx.y * 128, bcol = blockIdx.x * 128;
    const int wm = (w >> 1) * 64;
    const int wn = (w & 1) * 64;
    const int lrow = lane & 15;
    const int lcol = (lane >> 4) * 16;

    const int nch = K >> 5;

    float acc[4][8][4] = {};

    prefetch_chunk1(A, BT, brow, bcol, K, 0, sb, tid);
    CP_COMMIT();
    prefetch_chunk1(A, BT, brow, bcol, K, 32, sb + G1_STAGE, tid);
    CP_COMMIT();
    CP_WAIT1();
    __syncthreads();

    int s_cur = 0;
    for (int c = 0; c < nch; c++) {
        if (c + 2 < nch) {
            int s2 = s_cur + 2; if (s2 >= 3) s2 -= 3;
            prefetch_chunk1(A, BT, brow, bcol, K, (c + 2) << 5,
                            sb + s2 * G1_STAGE, tid);
            CP_COMMIT();
        }

        unsigned base = sb + s_cur * G1_STAGE;
        #pragma unroll
        for (int ks = 0; ks < 2; ks++) {
            int kb = ks * 32;
            unsigned bF[4][4];
            #pragma unroll
            for (int j2 = 0; j2 < 4; j2++) {
                unsigned off = (unsigned)((wn + j2 * 16 + lrow) * 64 + kb + lcol);
                LDMX4(bF[j2][0], bF[j2][1], bF[j2][2], bF[j2][3], base + 8192 + SWZ64(off));
            }
            #pragma unroll
            for (int i = 0; i < 4; i++) {
                unsigned off = (unsigned)((wm + i * 16 + lrow) * 64 + kb + lcol);
                unsigned aF[4];
                LDMX4(aF[0], aF[1], aF[2], aF[3], base + SWZ64(off));
                #pragma unroll
                for (int j = 0; j < 8; j++) {
                    unsigned b0 = (j & 1) ? bF[j >> 1][1] : bF[j >> 1][0];
                    unsigned b1 = (j & 1) ? bF[j >> 1][3] : bF[j >> 1][2];
                    MMAF16(acc[i][j], aF, b0, b1);
                }
            }
        }

        if (c + 1 < nch) {
            if (c + 2 < nch) { CP_WAIT1(); } else { CP_WAIT0(); }
        }
        __syncthreads();
        if (++s_cur == 3) s_cur = 0;
    }

    const int r0 = brow + wm + (lane >> 2);
    const int c0 = bcol + wn + (lane & 3) * 2;
    const bool splitOut = (C == nullptr) && (bcol < DD);
    #pragma unroll
    for (int i = 0; i < 4; i++) {
        #pragma unroll
        for (int j = 0; j < 8; j++) {
            int col = c0 + j * 8;
            float bx = bias[col], by = bias[col + 1];
            float v00 = acc[i][j][0] + bx, v01 = acc[i][j][1] + by;
            float v10 = acc[i][j][2] + bx, v11 = acc[i][j][3] + by;
            size_t o0 = (size_t)(r0 + i * 16) * Nstr + col;
            size_t o1 = (size_t)(r0 + i * 16 + 8) * Nstr + col;
            if (C) {
                *(float2*)&C[o0] = make_float2(v00, v01);
                *(float2*)&C[o1] = make_float2(v10, v11);
            } else if (splitOut) {
                unsigned l0, l1;
                unsigned h0 = packh2(v00, v01, l0);
                unsigned h1 = packh2(v10, v11, l1);
                *(unsigned*)&Chi[o0] = h0;
                *(unsigned*)&Clo[o0] = l0;
                *(unsigned*)&Chi[o1] = h1;
                *(unsigned*)&Clo[o1] = l1;
            } else {
                *(unsigned*)&Chi[o0] = packs2(v00, v01);
                *(unsigned*)&Chi[o1] = packs2(v10, v11);
            }
        }
    }
}

// ---------------------------------------------------------------------------
// Fused attention: QK^T (2-pass) + register softmax + AV, one kernel.
// QT=16, 128 threads, occ 2.
// smem: [0,49152) K triple-buffer (phase1) -> V triple-buffer 3x8KB (AV)
//       [49152,115200) logits fp32 rows (4128B) -> P fp16 in-place
// ---------------------------------------------------------------------------
#define LA_KV 0
#define LA_LF 49152
#define LA_TOTAL 115200
#define PSTRB 4128

__device__ __forceinline__ void la_load_k(
    const __half* __restrict__ qh, int b, int h, int kb, unsigned dst, int tid)
{
    #pragma unroll
    for (int i = 0; i < 8; i++) {
        int idx = tid + i * 128;
        int row = idx >> 3, c16 = (idx & 7) * 16;
        unsigned so = SWZ128((unsigned)(row * 128 + c16));
        CP_ASYNC16(dst + so, (const char*)(qh + (size_t)(b * SS + kb + row) * 3072 + 1024 + h * 64) + c16);
    }
}

// V chunk: 64 dims x 64 keys = [64 rows][128B], SWZ128
__device__ __forceinline__ void la_load_v(
    const __half* __restrict__ vTh, int bh, int kt, unsigned dst, int tid)
{
    #pragma unroll
    for (int i = 0; i < 4; i++) {
        int idx = tid + i * 128;
        int row = idx >> 3, c16 = (idx & 7) * 16;
        unsigned so = SWZ128((unsigned)(row * 128 + c16));
        CP_ASYNC16(dst + so, (const char*)(vTh + (size_t)(bh * HDIM + row) * SS + kt) + c16);
    }
}

__global__ __launch_bounds__(128, 2) void attn_fused(
    const __half* __restrict__ qh, const __half* __restrict__ ql,
    const __half* __restrict__ vTh,
    float* __restrict__ attn_out, __half* __restrict__ vh_out)
{
    extern __shared__ char smem[];
    unsigned sb = smem_u32(smem);

    const int qt = blockIdx.x, h = blockIdx.y, b = blockIdx.z;
    const int bh = b * HH + h;
    const int q0 = qt * 16;
    const int tid = threadIdx.x, w = tid >> 5, lane = tid & 31;
    const int lrow = lane & 15, lcol = (lane >> 4) * 16;
    const int wn = w * 32;     // phase-1 N offset (32 keys/warp)
    const int wnv = w * 16;    // AV N offset (16 dims/warp)

    // ---- prologue: Q (into LF temp) + K chunks 0,1
    {
        int row = tid >> 3, c16 = (tid & 7) * 16;
        unsigned so = SWZ128((unsigned)(row * 128 + c16));
        CP_ASYNC16(sb + LA_LF + so, (const char*)(qh + (size_t)(b * SS + q0 + row) * 3072 + h * 64) + c16);
        CP_ASYNC16(sb + LA_LF + 2048 + so, (const char*)(ql + (size_t)(b * SS + q0 + row) * 3072 + h * 64) + c16);
    }
    la_load_k(qh, b, h, 0, sb + LA_KV, tid);
    CP_COMMIT();
    la_load_k(qh, b, h, 128, sb + LA_KV + 16384, tid);
    CP_COMMIT();
    CP_WAIT1();
    __syncthreads();

    // ---- Q fragments -> registers
    unsigned qHf[4][4], qLf[4][4];
    #pragma unroll
    for (int ks = 0; ks < 4; ks++) {
        unsigned aoff = SWZ128((unsigned)(lrow * 128 + ks * 32 + lcol));
        LDMX4(qHf[ks][0], qHf[ks][1], qHf[ks][2], qHf[ks][3], sb + LA_LF + aoff);
        LDMX4(qLf[ks][0], qLf[ks][1], qLf[ks][2], qLf[ks][3], sb + LA_LF + 2048 + aoff);
    }
    __syncthreads();

    // ---- phase 1: QK^T, 8 chunks of 128 keys, K triple-buffered
    for (int c = 0; c < 8; c++) {
        if (c + 2 < 8) {
            int s2 = (c + 2) % 3;
            la_load_k(qh, b, h, (c + 2) * 128, sb + LA_KV + s2 * 16384, tid);
            CP_COMMIT();
        } else if (c == 7) {
            // stage 0 region free (chunk 6 done) -> prefetch V chunks 0,1
            la_load_v(vTh, bh, 0, sb + LA_KV, tid);
            CP_COMMIT();
            la_load_v(vTh, bh, 64, sb + LA_KV + 8192, tid);
            CP_COMMIT();
        }
        unsigned base = sb + LA_KV + (c % 3) * 16384;
        float acc[4][4] = {};
        #pragma unroll
        for (int ks = 0; ks < 4; ks++) {
            int kb = ks * 32;
            unsigned bF[2][4];
            #pragma unroll
            for (int j2 = 0; j2 < 2; j2++) {
                unsigned boff = SWZ128((unsigned)((wn + j2 * 16 + lrow) * 128 + kb + lcol));
                LDMX4(bF[j2][0], bF[j2][1], bF[j2][2], bF[j2][3], base + boff);
            }
            #pragma unroll
            for (int j = 0; j < 4; j++) {
                unsigned b0 = (j & 1) ? bF[j >> 1][1] : bF[j >> 1][0];
                unsigned b1 = (j & 1) ? bF[j >> 1][3] : bF[j >> 1][2];
                MMAF16(acc[j], qHf[ks], b0, b1);
                MMAF16(acc[j], qLf[ks], b0, b1);
            }
        }
        int r0 = lane >> 2;
        int cb = c * 128 + wn + (lane & 3) * 2;
        #pragma unroll
        for (int j = 0; j < 4; j++) {
            int col = cb + j * 8;
            *(float2*)(smem + LA_LF + r0 * PSTRB + col * 4) =
                make_float2(acc[j][0] * 0.125f, acc[j][1] * 0.125f);
            *(float2*)(smem + LA_LF + (r0 + 8) * PSTRB + col * 4) =
                make_float2(acc[j][2] * 0.125f, acc[j][3] * 0.125f);
        }
        if (c >= 5 && c < 7) { CP_WAIT0(); }          // K chunks fully landed
        else if (c + 1 < 8) { CP_WAIT1(); }           // deep pipeline
        __syncthreads();
    }

    // ---- register softmax; attn_out + P fp16 in-place into LF rows
    for (int r = w; r < 16; r += 4) {
        const char* rowp = smem + LA_LF + r * PSTRB;
        float e[32];
        float m = -1e30f;
        #pragma unroll
        for (int it = 0; it < 8; it++) {
            float4 v = *(const float4*)(rowp + it * 512 + lane * 16);
            e[it * 4 + 0] = v.x; e[it * 4 + 1] = v.y;
            e[it * 4 + 2] = v.z; e[it * 4 + 3] = v.w;
            m = fmaxf(m, fmaxf(fmaxf(v.x, v.y), fmaxf(v.z, v.w)));
        }
        #pragma unroll
        for (int o = 16; o > 0; o >>= 1) m = fmaxf(m, __shfl_xor_sync(0xFFFFFFFFu, m, o));
        float sum = 0.f;
        #pragma unroll
        for (int i = 0; i < 32; i++) {
            e[i] = __expf(e[i] - m);
            sum += e[i];
        }
        #pragma unroll
        for (int o = 16; o > 0; o >>= 1) sum += __shfl_xor_sync(0xFFFFFFFFu, sum, o);
        float inv = 1.0f / sum;
        size_t base = ((size_t)(bh * SS) + q0 + r) * SS;
        #pragma unroll
        for (int it = 0; it < 8; it++) {
            float4 o4;
            o4.x = e[it * 4 + 0] * inv;
            o4.y = e[it * 4 + 1] * inv;
            o4.z = e[it * 4 + 2] * inv;
            o4.w = e[it * 4 + 3] * inv;
            *(float4*)&attn_out[base + it * 128 + lane * 4] = o4;
            *(uint2*)(smem + LA_LF + r * PSTRB + it * 256 + lane * 8) =
                make_uint2(packs2(o4.x, o4.y), packs2(o4.z, o4.w));
        }
    }
    CP_WAIT1();          // V chunk 0 landed (chunk 1 may still be in flight)
    __syncthreads();     // all P rows visible

    // ---- AV phase: 16 chunks of 64 keys, V triple-buffered at LA_KV
    float vac[2][4] = {};
    for (int c = 0; c < 16; c++) {
        if (c + 2 < 16) {
            la_load_v(vTh, bh, (c + 2) * 64, sb + LA_KV + ((c + 2) % 3) * 8192, tid);
            CP_COMMIT();
        }
        unsigned vbase = sb + LA_KV + (c % 3) * 8192;
        #pragma unroll
        for (int ks = 0; ks < 4; ks++) {
            int kb = ks * 32;
            // A: P rows 0..15 at stride PSTRB (fp16, unswizzled)
            unsigned aF[4];
            LDMX4(aF[0], aF[1], aF[2], aF[3],
                  sb + LA_LF + (unsigned)(lrow * PSTRB + c * 128 + kb + lcol));
            // B: V dims wnv..wnv+15
            unsigned bF[4];
            LDMX4(bF[0], bF[1], bF[2], bF[3],
                  vbase + SWZ128((unsigned)((wnv + lrow) * 128 + kb + lcol)));
            MMAF16(vac[0], aF, bF[0], bF[2]);
            MMAF16(vac[1], aF, bF[1], bF[3]);
        }
        if (c + 1 < 16) {
            if (c + 2 < 16) { CP_WAIT1(); } else { CP_WAIT0(); }
        }
        __syncthreads();
    }

    // ---- epilogue: values fp16 (head-interleaved)
    {
        int r0 = lane >> 2;
        int c0 = wnv + (lane & 3) * 2;
        #pragma unroll
        for (int j = 0; j < 2; j++) {
            int col = h * 64 + c0 + j * 8;
            size_t o0 = (size_t)(b * SS + q0 + r0) * DD + col;
            size_t o1 = (size_t)(b * SS + q0 + r0 + 8) * DD + col;
            *(unsigned*)&vh_out[o0] = packs2(vac[j][0], vac[j][1]);
            *(unsigned*)&vh_out[o1] = packs2(vac[j][2], vac[j][3]);
        }
    }
}

// ---------------------------------------------------------------------------
extern "C" void kernel_launch(void* const* d_in, const int* in_sizes, int n_in,
                              void* d_out, int out_size)
{
    const float* x     = (const float*)d_in[0];
    const float* W_qkv = (const float*)d_in[1];
    const float* b_qkv = (const float*)d_in[2];
    const float* W_o   = (const float*)d_in[3];
    const float* b_o   = (const float*)d_in[4];

    float* out_o    = (float*)d_out;
    float* out_attn = (float*)d_out + (size_t)BB * SS * DD;

    __half *xh, *wqT, *woT, *vh, *qhp, *qlp, *vthp;
    float* bq;
    cudaGetSymbolAddress((void**)&xh, g_xh);
    cudaGetSymbolAddress((void**)&wqT, g_wqT);
    cudaGetSymbolAddress((void**)&woT, g_woT);
    cudaGetSymbolAddress((void**)&vh, g_vh);
    cudaGetSymbolAddress((void**)&qhp, g_qh);
    cudaGetSymbolAddress((void**)&qlp, g_ql);
    cudaGetSymbolAddress((void**)&vthp, g_vTh);
    cudaGetSymbolAddress((void**)&bq, g_bq);

    cudaFuncSetAttribute(gemm1x_mma, cudaFuncAttributeMaxDynamicSharedMemorySize, G1_TOTAL);
    cudaFuncSetAttribute(attn_fused, cudaFuncAttributeMaxDynamicSharedMemorySize, LA_TOTAL);

    // 0) prep: convert x; permuted W_qkv^T (+bias); W_o^T
    {
        int n4 = BB * SS * DD / 4;
        cvt_kernel<<<(n4 + 255) / 256, 256>>>(x, xh, n4);
        dim3 g1(3 * DD / 32, DD / 32);
        tsingle_kernel<<<g1, dim3(32, 8)>>>(W_qkv, wqT, DD, 3 * DD, 1, b_qkv, bq);
        dim3 g2(DD / 32, DD / 32);
        tsingle_kernel<<<g2, dim3(32, 8)>>>(W_o, woT, DD, DD, 0,
                                            (const float*)nullptr, (float*)nullptr);
    }

    // 1) QKV projection: one 1-pass gemm; Q-cols hi/lo, K/V single fp16
    {
        dim3 grid(3 * DD / 128, BB * SS / 128);
        gemm1x_mma<<<grid, 128, G1_TOTAL>>>(xh, wqT, bq, (float*)nullptr,
                                            qhp, qlp, BB * SS, 3 * DD, DD);
    }

    // 2) V^T (fp16 transpose of V block)
    {
        dim3 gv(SS / 32, HDIM / 32, BB * HH);
        vT_kernel<<<gv, dim3(32, 8)>>>(qhp, vthp);
    }

    // 3) fused attention: QK^T + softmax + AV
    {
        dim3 grid(SS / 16, HH, BB);
        attn_fused<<<grid, 128, LA_TOTAL>>>(qhp, qlp, vthp, out_attn, vh);
    }

    // 4) O-proj (1-pass fp16, fp32 out)
    {
        dim3 grid(DD / 128, BB * SS / 128);
        gemm1x_mma<<<grid, 128, G1_TOTAL>>>(vh, woT, b_o, out_o,
                                            (__half*)nullptr, (__half*)nullptr,
                                            BB * SS, DD, DD);
    }
}

// round 17
// speedup vs baseline: 1.0707x; 1.0707x over previous
#include <cuda_runtime.h>
#include <cuda_bf16.h>
#include <cuda_fp16.h>

#define BB 4
#define SS 1024
#define HH 16
#define HDIM 64
#define DD 1024

// ---------------------------------------------------------------------------
// scratch (device globals — no allocation allowed)
// ---------------------------------------------------------------------------
__device__ __half g_xh[BB * SS * DD];           // x fp16
__device__ __half g_wqT[3 * DD * DD];           // W_qkv^T fp16, permuted rows [Q|K|V]
__device__ float  g_bq[3 * DD];                 // permuted bias
__device__ __half g_woT[DD * DD];               // W_o^T fp16
__device__ __half g_vh[BB * SS * DD];           // values fp16 (av epilogue)
__device__ __half g_qh[BB * SS * 3 * DD];       // qkv hi, permuted cols [Q|K|V]
__device__ __half g_ql[BB * SS * 3 * DD];       // qkv lo (only Q cols used)
__device__ __half g_vTh[BB * HH * HDIM * SS];   // V^T fp16 per (b,h): [64][S]
__device__ __half g_p[(size_t)BB * HH * SS * SS]; // normalized attention fp16

// ---------------------------------------------------------------------------
__device__ __forceinline__ unsigned smem_u32(const void* p) {
    unsigned a;
    asm("{ .reg .u64 t; cvta.to.shared.u64 t, %1; cvt.u32.u64 %0, t; }" : "=r"(a) : "l"(p));
    return a;
}
#define SWZ128(o) ((o) ^ (((o) >> 3) & 0x70))
#define SWZ64(o)  ((o) ^ (((o) >> 3) & 0x30))

#define CP_ASYNC16(saddr, gptr) \
    asm volatile("cp.async.cg.shared.global [%0], [%1], 16;" :: "r"(saddr), "l"(gptr) : "memory")
#define CP_COMMIT() asm volatile("cp.async.commit_group;" ::: "memory")
#define CP_WAIT1()  asm volatile("cp.async.wait_group 1;" ::: "memory")
#define CP_WAIT0()  asm volatile("cp.async.wait_group 0;" ::: "memory")

#define LDMX4(r0, r1, r2, r3, a) \
    asm volatile("ldmatrix.sync.aligned.m8n8.x4.shared.b16 {%0,%1,%2,%3}, [%4];" \
        : "=r"(r0), "=r"(r1), "=r"(r2), "=r"(r3) : "r"(a))

#define MMAF16(d, a, b0, b1) \
    asm volatile("mma.sync.aligned.m16n8k16.row.col.f32.f16.f16.f32 " \
        "{%0,%1,%2,%3}, {%4,%5,%6,%7}, {%8,%9}, {%0,%1,%2,%3};" \
        : "+f"((d)[0]), "+f"((d)[1]), "+f"((d)[2]), "+f"((d)[3]) \
        : "r"((a)[0]), "r"((a)[1]), "r"((a)[2]), "r"((a)[3]), "r"(b0), "r"(b1))

// streaming store (evict-first): attn output is write-once, never re-read
#define STG_CS4(ptr, v) \
    asm volatile("st.global.cs.v4.f32 [%0], {%1,%2,%3,%4};" \
        :: "l"(ptr), "f"((v).x), "f"((v).y), "f"((v).z), "f"((v).w) : "memory")

__device__ __forceinline__ unsigned packh2(float x, float y, unsigned& lo) {
    __half hx = __float2half(x);
    __half hy = __float2half(y);
    __half lx = __float2half(x - __half2float(hx));
    __half ly = __float2half(y - __half2float(hy));
    lo = ((unsigned)__half_as_ushort(ly) << 16) | __half_as_ushort(lx);
    return ((unsigned)__half_as_ushort(hy) << 16) | __half_as_ushort(hx);
}
__device__ __forceinline__ unsigned packs2(float x, float y) {
    return ((unsigned)__half_as_ushort(__float2half(y)) << 16) |
           __half_as_ushort(__float2half(x));
}
__device__ __forceinline__ int qkv_perm(int n) {
    int head = n / 192, wi = n % 192;
    return (wi / 64) * 1024 + head * 64 + (wi % 64);
}

// ---------------------------------------------------------------------------
__global__ __launch_bounds__(256) void cvt_kernel(
    const float* __restrict__ src, __half* __restrict__ dst, int n4)
{
    int i = blockIdx.x * 256 + threadIdx.x;
    if (i >= n4) return;
    float4 v = ((const float4*)src)[i];
    ((uint2*)dst)[i] = make_uint2(packs2(v.x, v.y), packs2(v.z, v.w));
}

__global__ __launch_bounds__(256) void tsingle_kernel(
    const float* __restrict__ W, __half* __restrict__ WT, int K, int N, int permute,
    const float* __restrict__ b, float* __restrict__ bp)
{
    __shared__ float t[32][33];
    int k0 = blockIdx.y * 32, n0 = blockIdx.x * 32;
    int tx = threadIdx.x, ty = threadIdx.y;
    #pragma unroll
    for (int i = 0; i < 32; i += 8)
        t[ty + i][tx] = W[(size_t)(k0 + ty + i) * N + n0 + tx];
    __syncthreads();
    #pragma unroll
    for (int i = 0; i < 32; i += 8) {
        int n = n0 + ty + i;
        int np = permute ? qkv_perm(n) : n;
        WT[(size_t)np * K + k0 + tx] = __float2half(t[tx][ty + i]);
    }
    if (b && blockIdx.y == 0) {
        int tid = ty * 32 + tx;
        if (tid < 32) {
            int n = n0 + tid;
            bp[permute ? qkv_perm(n) : n] = b[n];
        }
    }
}

__global__ __launch_bounds__(256) void vT_kernel(
    const __half* __restrict__ qh, __half* __restrict__ vTh)
{
    __shared__ __half t[32][33];
    int s0 = blockIdx.x * 32, d0 = blockIdx.y * 32, bh = blockIdx.z;
    int b = bh >> 4, h = bh & 15;
    int tx = threadIdx.x, ty = threadIdx.y;
    #pragma unroll
    for (int i = 0; i < 32; i += 8)
        t[ty + i][tx] = qh[(size_t)(b * SS + s0 + ty + i) * 3072 + 2048 + h * 64 + d0 + tx];
    __syncthreads();
    #pragma unroll
    for (int i = 0; i < 32; i += 8)
        vTh[(size_t)(bh * HDIM + d0 + ty + i) * SS + s0 + tx] = t[tx][ty + i];
}

// ---------------------------------------------------------------------------
__device__ __forceinline__ void gload64h(const __half* __restrict__ src,
                                         int rbase, int K, int kt, unsigned dst, int tid)
{
    #pragma unroll
    for (int i = 0; i < 4; i++) {
        int idx = tid + i * 128;
        int row = idx >> 2;
        int c16 = (idx & 3) * 16;
        CP_ASYNC16(dst + SWZ64((unsigned)(row * 64 + c16)),
                   (const char*)(src + (size_t)(rbase + row) * K + kt) + c16);
    }
}

// ---------------------------------------------------------------------------
// 1-pass fp16 GEMM: C fp32 | Q-cols hi/lo split | single fp16 (per bcol)
// ---------------------------------------------------------------------------
#define G1_STAGE 16384
#define G1_TOTAL 49152

__device__ __forceinline__ void prefetch_chunk1(
    const __half* __restrict__ A, const __half* __restrict__ BT,
    int brow, int bcol, int K, int kt, unsigned stage, int tid)
{
    gload64h(A, brow, K, kt, stage, tid);
    gload64h(BT, bcol, K, kt, stage + 8192, tid);
}

__global__ __launch_bounds__(128, 2) void gemm1x_mma(
    const __half* __restrict__ A, const __half* __restrict__ BT,
    const float* __restrict__ bias, float* __restrict__ C,
    __half* __restrict__ Chi, __half* __restrict__ Clo,
    int M, int Nstr, int K)
{
    extern __shared__ char smem[];
    unsigned sb = smem_u32(smem);
    const int tid = threadIdx.x, w = tid >> 5, lane = tid & 31;
    const int brow = blockIdx.y * 128, bcol = blockIdx.x * 128;
    const int wm = (w >> 1) * 64;
    const int wn = (w & 1) * 64;
    const int lrow = lane & 15;
    const int lcol = (lane >> 4) * 16;

    const int nch = K >> 5;

    float acc[4][8][4] = {};

    prefetch_chunk1(A, BT, brow, bcol, K, 0, sb, tid);
    CP_COMMIT();
    prefetch_chunk1(A, BT, brow, bcol, K, 32, sb + G1_STAGE, tid);
    CP_COMMIT();
    CP_WAIT1();
    __syncthreads();

    int s_cur = 0;
    for (int c = 0; c < nch; c++) {
        if (c + 2 < nch) {
            int s2 = s_cur + 2; if (s2 >= 3) s2 -= 3;
            prefetch_chunk1(A, BT, brow, bcol, K, (c + 2) << 5,
                            sb + s2 * G1_STAGE, tid);
            CP_COMMIT();
        }

        unsigned base = sb + s_cur * G1_STAGE;
        #pragma unroll
        for (int ks = 0; ks < 2; ks++) {
            int kb = ks * 32;
            unsigned bF[4][4];
            #pragma unroll
            for (int j2 = 0; j2 < 4; j2++) {
                unsigned off = (unsigned)((wn + j2 * 16 + lrow) * 64 + kb + lcol);
                LDMX4(bF[j2][0], bF[j2][1], bF[j2][2], bF[j2][3], base + 8192 + SWZ64(off));
            }
            #pragma unroll
            for (int i = 0; i < 4; i++) {
                unsigned off = (unsigned)((wm + i * 16 + lrow) * 64 + kb + lcol);
                unsigned aF[4];
                LDMX4(aF[0], aF[1], aF[2], aF[3], base + SWZ64(off));
                #pragma unroll
                for (int j = 0; j < 8; j++) {
                    unsigned b0 = (j & 1) ? bF[j >> 1][1] : bF[j >> 1][0];
                    unsigned b1 = (j & 1) ? bF[j >> 1][3] : bF[j >> 1][2];
                    MMAF16(acc[i][j], aF, b0, b1);
                }
            }
        }

        if (c + 1 < nch) {
            if (c + 2 < nch) { CP_WAIT1(); } else { CP_WAIT0(); }
        }
        __syncthreads();
        if (++s_cur == 3) s_cur = 0;
    }

    const int r0 = brow + wm + (lane >> 2);
    const int c0 = bcol + wn + (lane & 3) * 2;
    const bool splitOut = (C == nullptr) && (bcol < DD);
    #pragma unroll
    for (int i = 0; i < 4; i++) {
        #pragma unroll
        for (int j = 0; j < 8; j++) {
            int col = c0 + j * 8;
            float bx = bias[col], by = bias[col + 1];
            float v00 = acc[i][j][0] + bx, v01 = acc[i][j][1] + by;
            float v10 = acc[i][j][2] + bx, v11 = acc[i][j][3] + by;
            size_t o0 = (size_t)(r0 + i * 16) * Nstr + col;
            size_t o1 = (size_t)(r0 + i * 16 + 8) * Nstr + col;
            if (C) {
                *(float2*)&C[o0] = make_float2(v00, v01);
                *(float2*)&C[o1] = make_float2(v10, v11);
            } else if (splitOut) {
                unsigned l0, l1;
                unsigned h0 = packh2(v00, v01, l0);
                unsigned h1 = packh2(v10, v11, l1);
                *(unsigned*)&Chi[o0] = h0;
                *(unsigned*)&Clo[o0] = l0;
                *(unsigned*)&Chi[o1] = h1;
                *(unsigned*)&Clo[o1] = l1;
            } else {
                *(unsigned*)&Chi[o0] = packs2(v00, v01);
                *(unsigned*)&Chi[o1] = packs2(v10, v11);
            }
        }
    }
}

// ---------------------------------------------------------------------------
// Kernel A: QK^T (2-pass Q x K-hi) + register softmax, streaming attn stores.
// ---------------------------------------------------------------------------
#define LA_K0 0
#define LA_LF 49152
#define LA_TOTAL 115200
#define PSTRB 4128

__device__ __forceinline__ void la_load_k(
    const __half* __restrict__ qh, int b, int h, int kb, unsigned dst, int tid)
{
    #pragma unroll
    for (int i = 0; i < 8; i++) {
        int idx = tid + i * 128;
        int row = idx >> 3, c16 = (idx & 7) * 16;
        unsigned so = SWZ128((unsigned)(row * 128 + c16));
        CP_ASYNC16(dst + so, (const char*)(qh + (size_t)(b * SS + kb + row) * 3072 + 1024 + h * 64) + c16);
    }
}

__global__ __launch_bounds__(128, 2) void attn_logits(
    const __half* __restrict__ qh, const __half* __restrict__ ql,
    float* __restrict__ attn_out, __half* __restrict__ pOut)
{
    extern __shared__ char smem[];
    unsigned sb = smem_u32(smem);

    const int qt = blockIdx.x, h = blockIdx.y, b = blockIdx.z;
    const int bh = b * HH + h;
    const int q0 = qt * 16;
    const int tid = threadIdx.x, w = tid >> 5, lane = tid & 31;
    const int lrow = lane & 15, lcol = (lane >> 4) * 16;
    const int wn = w * 32;

    {
        int row = tid >> 3, c16 = (tid & 7) * 16;
        unsigned so = SWZ128((unsigned)(row * 128 + c16));
        CP_ASYNC16(sb + LA_LF + so, (const char*)(qh + (size_t)(b * SS + q0 + row) * 3072 + h * 64) + c16);
        CP_ASYNC16(sb + LA_LF + 2048 + so, (const char*)(ql + (size_t)(b * SS + q0 + row) * 3072 + h * 64) + c16);
    }
    la_load_k(qh, b, h, 0, sb + LA_K0, tid);
    CP_COMMIT();
    la_load_k(qh, b, h, 128, sb + LA_K0 + 16384, tid);
    CP_COMMIT();
    CP_WAIT1();
    __syncthreads();

    unsigned qHf[4][4], qLf[4][4];
    #pragma unroll
    for (int ks = 0; ks < 4; ks++) {
        unsigned aoff = SWZ128((unsigned)(lrow * 128 + ks * 32 + lcol));
        LDMX4(qHf[ks][0], qHf[ks][1], qHf[ks][2], qHf[ks][3], sb + LA_LF + aoff);
        LDMX4(qLf[ks][0], qLf[ks][1], qLf[ks][2], qLf[ks][3], sb + LA_LF + 2048 + aoff);
    }
    __syncthreads();

    for (int c = 0; c < 8; c++) {
        if (c + 2 < 8) {
            int s2 = (c + 2) % 3;
            la_load_k(qh, b, h, (c + 2) * 128, sb + LA_K0 + s2 * 16384, tid);
            CP_COMMIT();
        }
        unsigned base = sb + LA_K0 + (c % 3) * 16384;
        float acc[4][4] = {};
        #pragma unroll
        for (int ks = 0; ks < 4; ks++) {
            int kb = ks * 32;
            unsigned bF[2][4];
            #pragma unroll
            for (int j2 = 0; j2 < 2; j2++) {
                unsigned boff = SWZ128((unsigned)((wn + j2 * 16 + lrow) * 128 + kb + lcol));
                LDMX4(bF[j2][0], bF[j2][1], bF[j2][2], bF[j2][3], base + boff);
            }
            #pragma unroll
            for (int j = 0; j < 4; j++) {
                unsigned b0 = (j & 1) ? bF[j >> 1][1] : bF[j >> 1][0];
                unsigned b1 = (j & 1) ? bF[j >> 1][3] : bF[j >> 1][2];
                MMAF16(acc[j], qHf[ks], b0, b1);
                MMAF16(acc[j], qLf[ks], b0, b1);
            }
        }
        int r0 = lane >> 2;
        int cb = c * 128 + wn + (lane & 3) * 2;
        #pragma unroll
        for (int j = 0; j < 4; j++) {
            int col = cb + j * 8;
            *(float2*)(smem + LA_LF + r0 * PSTRB + col * 4) =
                make_float2(acc[j][0] * 0.125f, acc[j][1] * 0.125f);
            *(float2*)(smem + LA_LF + (r0 + 8) * PSTRB + col * 4) =
                make_float2(acc[j][2] * 0.125f, acc[j][3] * 0.125f);
        }
        if (c + 1 < 8) {
            if (c + 2 < 8) { CP_WAIT1(); } else { CP_WAIT0(); }
        }
        __syncthreads();
    }

    // register-resident softmax; streaming attn stores, normal P stores
    for (int r = w; r < 16; r += 4) {
        const char* rowp = smem + LA_LF + r * PSTRB;
        float e[32];
        float m = -1e30f;
        #pragma unroll
        for (int it = 0; it < 8; it++) {
            float4 v = *(const float4*)(rowp + it * 512 + lane * 16);
            e[it * 4 + 0] = v.x; e[it * 4 + 1] = v.y;
            e[it * 4 + 2] = v.z; e[it * 4 + 3] = v.w;
            m = fmaxf(m, fmaxf(fmaxf(v.x, v.y), fmaxf(v.z, v.w)));
        }
        #pragma unroll
        for (int o = 16; o > 0; o >>= 1) m = fmaxf(m, __shfl_xor_sync(0xFFFFFFFFu, m, o));
        float sum = 0.f;
        #pragma unroll
        for (int i = 0; i < 32; i++) {
            e[i] = __expf(e[i] - m);
            sum += e[i];
        }
        #pragma unroll
        for (int o = 16; o > 0; o >>= 1) sum += __shfl_xor_sync(0xFFFFFFFFu, sum, o);
        float inv = 1.0f / sum;
        size_t base = ((size_t)(bh * SS) + q0 + r) * SS;
        #pragma unroll
        for (int it = 0; it < 8; it++) {
            float4 o4;
            o4.x = e[it * 4 + 0] * inv;
            o4.y = e[it * 4 + 1] * inv;
            o4.z = e[it * 4 + 2] * inv;
            o4.w = e[it * 4 + 3] * inv;
            STG_CS4(&attn_out[base + it * 128 + lane * 4], o4);
            *(uint2*)&pOut[base + it * 128 + lane * 4] =
                make_uint2(packs2(o4.x, o4.y), packs2(o4.z, o4.w));
        }
    }
}

// ---------------------------------------------------------------------------
// Kernel B: values = P(fp16) @ V^T (fp16 single)
// ---------------------------------------------------------------------------
#define AV_STAGE 24576
#define AV_TOTAL 73728

__device__ __forceinline__ void av_load(
    const __half* __restrict__ P, const __half* __restrict__ vTh,
    int bh, int brow, int kt, unsigned stage, int tid)
{
    #pragma unroll
    for (int i = 0; i < 8; i++) {
        int idx = tid + i * 128;
        int row = idx >> 3, c16 = (idx & 7) * 16;
        unsigned so = SWZ128((unsigned)(row * 128 + c16));
        CP_ASYNC16(stage + so, (const char*)(P + ((size_t)(bh * SS + brow + row)) * SS + kt) + c16);
    }
    #pragma unroll
    for (int i = 0; i < 4; i++) {
        int idx = tid + i * 128;
        int row = idx >> 3, c16 = (idx & 7) * 16;
        unsigned so = SWZ128((unsigned)(row * 128 + c16));
        CP_ASYNC16(stage + 16384 + so, (const char*)(vTh + (size_t)(bh * HDIM + row) * SS + kt) + c16);
    }
}

__global__ __launch_bounds__(128, 2) void av_gemm(
    const __half* __restrict__ P, const __half* __restrict__ vTh,
    __half* __restrict__ Vh)
{
    extern __shared__ char smem[];
    unsigned sb = smem_u32(smem);
    const int tid = threadIdx.x, w = tid >> 5, lane = tid & 31;
    const int brow = blockIdx.x * 128;
    const int bh = blockIdx.y;
    const int b = bh >> 4, h = bh & 15;
    const int wm = (w >> 1) * 64;
    const int wn = (w & 1) * 32;
    const int lrow = lane & 15;
    const int lcol = (lane >> 4) * 16;

    const int nch = 16;

    float acc[4][4][4] = {};

    av_load(P, vTh, bh, brow, 0, sb, tid);
    CP_COMMIT();
    av_load(P, vTh, bh, brow, 64, sb + AV_STAGE, tid);
    CP_COMMIT();
    CP_WAIT1();
    __syncthreads();

    int s_cur = 0;
    for (int c = 0; c < nch; c++) {
        if (c + 2 < nch) {
            int s2 = s_cur + 2; if (s2 >= 3) s2 -= 3;
            av_load(P, vTh, bh, brow, (c + 2) * 64, sb + s2 * AV_STAGE, tid);
            CP_COMMIT();
        }

        unsigned base = sb + s_cur * AV_STAGE;
        #pragma unroll
        for (int ks = 0; ks < 4; ks++) {
            int kb = ks * 32;
            unsigned vh[2][4];
            #pragma unroll
            for (int j2 = 0; j2 < 2; j2++) {
                unsigned off = SWZ128((unsigned)((wn + j2 * 16 + lrow) * 128 + kb + lcol));
                LDMX4(vh[j2][0], vh[j2][1], vh[j2][2], vh[j2][3], base + 16384 + off);
            }
            #pragma unroll
            for (int i = 0; i < 4; i++) {
                unsigned off = SWZ128((unsigned)((wm + i * 16 + lrow) * 128 + kb + lcol));
                unsigned aF[4];
                LDMX4(aF[0], aF[1], aF[2], aF[3], base + off);
                #pragma unroll
                for (int j = 0; j < 4; j++) {
                    unsigned h0 = (j & 1) ? vh[j >> 1][1] : vh[j >> 1][0];
                    unsigned h1 = (j & 1) ? vh[j >> 1][3] : vh[j >> 1][2];
                    MMAF16(acc[i][j], aF, h0, h1);
                }
            }
        }

        if (c + 1 < nch) {
            if (c + 2 < nch) { CP_WAIT1(); } else { CP_WAIT0(); }
        }
        __syncthreads();
        if (++s_cur == 3) s_cur = 0;
    }

    const int r0 = brow + wm + (lane >> 2);
    const int c0 = wn + (lane & 3) * 2;
    #pragma unroll
    for (int i = 0; i < 4; i++) {
        #pragma unroll
        for (int j = 0; j < 4; j++) {
            int col = h * 64 + c0 + j * 8;
            size_t o0 = (size_t)(b * SS + r0 + i * 16) * DD + col;
            size_t o1 = (size_t)(b * SS + r0 + i * 16 + 8) * DD + col;
            *(unsigned*)&Vh[o0] = packs2(acc[i][j][0], acc[i][j][1]);
            *(unsigned*)&Vh[o1] = packs2(acc[i][j][2], acc[i][j][3]);
        }
    }
}

// ---------------------------------------------------------------------------
extern "C" void kernel_launch(void* const* d_in, const int* in_sizes, int n_in,
                              void* d_out, int out_size)
{
    const float* x     = (const float*)d_in[0];
    const float* W_qkv = (const float*)d_in[1];
    const float* b_qkv = (const float*)d_in[2];
    const float* W_o   = (const float*)d_in[3];
    const float* b_o   = (const float*)d_in[4];

    float* out_o    = (float*)d_out;
    float* out_attn = (float*)d_out + (size_t)BB * SS * DD;

    __half *xh, *wqT, *woT, *vh, *qhp, *qlp, *vthp, *pp;
    float* bq;
    cudaGetSymbolAddress((void**)&xh, g_xh);
    cudaGetSymbolAddress((void**)&wqT, g_wqT);
    cudaGetSymbolAddress((void**)&woT, g_woT);
    cudaGetSymbolAddress((void**)&vh, g_vh);
    cudaGetSymbolAddress((void**)&qhp, g_qh);
    cudaGetSymbolAddress((void**)&qlp, g_ql);
    cudaGetSymbolAddress((void**)&vthp, g_vTh);
    cudaGetSymbolAddress((void**)&pp, g_p);
    cudaGetSymbolAddress((void**)&bq, g_bq);

    cudaFuncSetAttribute(gemm1x_mma, cudaFuncAttributeMaxDynamicSharedMemorySize, G1_TOTAL);
    cudaFuncSetAttribute(attn_logits, cudaFuncAttributeMaxDynamicSharedMemorySize, LA_TOTAL);
    cudaFuncSetAttribute(av_gemm, cudaFuncAttributeMaxDynamicSharedMemorySize, AV_TOTAL);

    // 0) prep: convert x; permuted W_qkv^T (+bias); W_o^T
    {
        int n4 = BB * SS * DD / 4;
        cvt_kernel<<<(n4 + 255) / 256, 256>>>(x, xh, n4);
        dim3 g1(3 * DD / 32, DD / 32);
        tsingle_kernel<<<g1, dim3(32, 8)>>>(W_qkv, wqT, DD, 3 * DD, 1, b_qkv, bq);
        dim3 g2(DD / 32, DD / 32);
        tsingle_kernel<<<g2, dim3(32, 8)>>>(W_o, woT, DD, DD, 0,
                                            (const float*)nullptr, (float*)nullptr);
    }

    // 1) QKV projection: one 1-pass gemm; Q-cols hi/lo, K/V single fp16
    {
        dim3 grid(3 * DD / 128, BB * SS / 128);
        gemm1x_mma<<<grid, 128, G1_TOTAL>>>(xh, wqT, bq, (float*)nullptr,
                                            qhp, qlp, BB * SS, 3 * DD, DD);
    }

    // 2) V^T (fp16 transpose of V block)
    {
        dim3 gv(SS / 32, HDIM / 32, BB * HH);
        vT_kernel<<<gv, dim3(32, 8)>>>(qhp, vthp);
    }

    // 3a) QK^T + register softmax -> attention (streaming) + P fp16
    {
        dim3 grid(SS / 16, HH, BB);
        attn_logits<<<grid, 128, LA_TOTAL>>>(qhp, qlp, out_attn, pp);
    }

    // 3b) AV gemm -> values fp16
    {
        dim3 grid(SS / 128, BB * HH);
        av_gemm<<<grid, 128, AV_TOTAL>>>(pp, vthp, vh);
    }

    // 4) O-proj (1-pass fp16, fp32 out)
    {
        dim3 grid(DD / 128, BB * SS / 128);
        gemm1x_mma<<<grid, 128, G1_TOTAL>>>(vh, woT, b_o, out_o,
                                            (__half*)nullptr, (__half*)nullptr,
                                            BB * SS, DD, DD);
    }
}